// round 1
// baseline (speedup 1.0000x reference)
#include <cuda_runtime.h>
#include <math.h>

#define BB 32
#define NN 32768
#define DD 128
#define TN 128
#define NBLK (NN / TN)   // 256

// Scratch (no allocations allowed in kernel_launch)
__device__ float g_logits[(size_t)BB * NN];       // 4 MB
__device__ float g_m[BB];
__device__ float g_z[BB];
__device__ float g_partial[NBLK][BB * DD];        // 4 MB

// ---------------------------------------------------------------------------
// Kernel A: logits[b][n] = c1_b * (x_b . y_n) - c2_b * |y_n|^2
// Grid: NBLK blocks x 256 threads. Tile: 32 b x 128 n, k-chunked by 32.
// ---------------------------------------------------------------------------
__global__ __launch_bounds__(256) void logits_kernel(
    const float* __restrict__ x,       // [B, D]
    const float* __restrict__ alphas,  // [B]
    const float* __restrict__ y)       // [N, D]
{
    __shared__ float xs[BB][DD];       // 16 KB
    __shared__ float ys[TN][33];       // ~16.9 KB, pitch 33 => conflict-free
    __shared__ float nnorm[TN];

    const int tid  = threadIdx.x;
    const int lane = tid & 31;
    const int warp = tid >> 5;
    const int nbase = blockIdx.x * TN;

    // Load x [32,128] into smem (coalesced)
    for (int i = tid; i < BB * DD; i += 256) xs[i >> 7][i & 127] = x[i];
    if (tid < TN) nnorm[tid] = 0.f;

    const int ng = lane;        // n-group: thread covers n = ng + 32*j
    const int b0 = warp * 4;    // b-group: 4 consecutive b

    float acc[4][4];
#pragma unroll
    for (int i = 0; i < 4; i++)
#pragma unroll
        for (int j = 0; j < 4; j++) acc[i][j] = 0.f;

    for (int kc = 0; kc < DD; kc += 32) {
        __syncthreads();
        // Load y chunk [TN][32] (coalesced: lanes cover k), fuse |y|^2 partial
#pragma unroll
        for (int it = 0; it < TN / 8; it++) {
            const int n = warp + it * 8;
            float v = y[(size_t)(nbase + n) * DD + kc + lane];
            ys[n][lane] = v;
            float s = v * v;
#pragma unroll
            for (int o = 16; o > 0; o >>= 1) s += __shfl_xor_sync(0xffffffffu, s, o);
            if (lane == 0) nnorm[n] += s;
        }
        __syncthreads();

#pragma unroll
        for (int k = 0; k < 32; k++) {
            float yv[4];
#pragma unroll
            for (int j = 0; j < 4; j++) yv[j] = ys[ng + 32 * j][k];
#pragma unroll
            for (int i = 0; i < 4; i++) {
                const float xv = xs[b0 + i][kc + k];
#pragma unroll
                for (int j = 0; j < 4; j++) acc[i][j] = fmaf(xv, yv[j], acc[i][j]);
            }
        }
    }
    __syncthreads();

#pragma unroll
    for (int i = 0; i < 4; i++) {
        const int b = b0 + i;
        const float a   = alphas[b];
        const float var = 1.f - a;
        const float c1  = sqrtf(a) / var;
        const float c2  = a / (2.f * var);
#pragma unroll
        for (int j = 0; j < 4; j++) {
            const int n = ng + 32 * j;
            g_logits[(size_t)b * NN + nbase + n] = c1 * acc[i][j] - c2 * nnorm[n];
        }
    }
}

// ---------------------------------------------------------------------------
// Kernel B: per-b max and sum of exp(l - m). Grid: 32 blocks x 512 threads.
// ---------------------------------------------------------------------------
__global__ __launch_bounds__(512) void softmax_stats_kernel()
{
    const int b   = blockIdx.x;
    const int tid = threadIdx.x;
    const float* l = &g_logits[(size_t)b * NN];

    __shared__ float red[16];
    __shared__ float bcast;

    float m = -1e30f;
    for (int i = tid; i < NN; i += 512) m = fmaxf(m, l[i]);
#pragma unroll
    for (int o = 16; o > 0; o >>= 1) m = fmaxf(m, __shfl_xor_sync(0xffffffffu, m, o));
    if ((tid & 31) == 0) red[tid >> 5] = m;
    __syncthreads();
    if (tid == 0) {
        float v = red[0];
        for (int w = 1; w < 16; w++) v = fmaxf(v, red[w]);
        bcast = v;
    }
    __syncthreads();
    m = bcast;

    float z = 0.f;
    for (int i = tid; i < NN; i += 512) z += expf(l[i] - m);
#pragma unroll
    for (int o = 16; o > 0; o >>= 1) z += __shfl_xor_sync(0xffffffffu, z, o);
    __syncthreads();
    if ((tid & 31) == 0) red[tid >> 5] = z;
    __syncthreads();
    if (tid == 0) {
        float s = 0.f;
        for (int w = 0; w < 16; w++) s += red[w];
        g_m[b] = m;
        g_z[b] = s;
    }
}

// ---------------------------------------------------------------------------
// Kernel C: partial S[b][d] = sum_{n in chunk} exp(l-m) * y[n][d]
// Grid: NBLK blocks x 256 threads. Tile: 32 b x 128 d, n-chunked by 32.
// ---------------------------------------------------------------------------
__global__ __launch_bounds__(256) void wsum_kernel(const float* __restrict__ y)
{
    __shared__ float ps[BB][TN];       // 16 KB
    __shared__ float ys[32][129];      // 16.5 KB, pitch 129

    const int tid   = threadIdx.x;
    const int nbase = blockIdx.x * TN;

    // Unnormalized softmax weights for this n-chunk
    for (int t = tid; t < BB * TN; t += 256) {
        const int b = t >> 7, n = t & 127;
        ps[b][n] = expf(g_logits[(size_t)b * NN + nbase + n] - g_m[b]);
    }

    const int dg = tid & 31;           // d = dg + 32*j
    const int b0 = (tid >> 5) * 4;

    float acc[4][4];
#pragma unroll
    for (int i = 0; i < 4; i++)
#pragma unroll
        for (int j = 0; j < 4; j++) acc[i][j] = 0.f;

    for (int nc = 0; nc < TN; nc += 32) {
        __syncthreads();
        for (int t = tid; t < 32 * DD; t += 256) {
            const int n = t >> 7, d = t & 127;
            ys[n][d] = y[(size_t)(nbase + nc + n) * DD + d];
        }
        __syncthreads();

#pragma unroll
        for (int nn = 0; nn < 32; nn++) {
            float yv[4];
#pragma unroll
            for (int j = 0; j < 4; j++) yv[j] = ys[nn][dg + 32 * j];
#pragma unroll
            for (int i = 0; i < 4; i++) {
                const float pv = ps[b0 + i][nc + nn];
#pragma unroll
                for (int j = 0; j < 4; j++) acc[i][j] = fmaf(pv, yv[j], acc[i][j]);
            }
        }
    }

#pragma unroll
    for (int i = 0; i < 4; i++)
#pragma unroll
        for (int j = 0; j < 4; j++)
            g_partial[blockIdx.x][(b0 + i) * DD + dg + 32 * j] = acc[i][j];
}

// ---------------------------------------------------------------------------
// Kernel D: reduce partials, out = (x - sqrt(a)*x0) / sqrt(var)
// Grid: 32 blocks x 128 threads.
// ---------------------------------------------------------------------------
__global__ __launch_bounds__(128) void finalize_kernel(
    const float* __restrict__ x,
    const float* __restrict__ alphas,
    float* __restrict__ out)
{
    const int b = blockIdx.x;
    const int d = threadIdx.x;
    float s = 0.f;
#pragma unroll 8
    for (int c = 0; c < NBLK; c++) s += g_partial[c][b * DD + d];

    const float a   = alphas[b];
    const float var = 1.f - a;
    const float x0  = s / g_z[b];
    out[b * DD + d] = (x[b * DD + d] - sqrtf(a) * x0) / sqrtf(var);
}

// ---------------------------------------------------------------------------
extern "C" void kernel_launch(void* const* d_in, const int* in_sizes, int n_in,
                              void* d_out, int out_size)
{
    const float* inputs = (const float*)d_in[0];   // [B, D]
    const float* alphas = (const float*)d_in[1];   // [B]
    const float* data   = (const float*)d_in[2];   // [N, D]
    float* out = (float*)d_out;                    // [B, D]

    logits_kernel<<<NBLK, 256>>>(inputs, alphas, data);
    softmax_stats_kernel<<<BB, 512>>>();
    wsum_kernel<<<NBLK, 256>>>(data);
    finalize_kernel<<<BB, DD>>>(inputs, alphas, out);
}